// round 13
// baseline (speedup 1.0000x reference)
#include <cuda_runtime.h>
#include <cstdint>

// Problem constants:
//   x: [8, 128, 128, 128]  (B, D, H, W), HW = 16384, NPIX = 131072
//   C = 128, M = 1, NEG = 3  -> 512 prototypes total
// Output tuple flattened:
//   cls_score     @ 0         (16777216)
//   distances     @ 16777216  (16777216)
//   distances_neg @ 33554432  (50331648)
//   probs_ori     @ 83886080  (16777216)

typedef unsigned long long ull;

// Prototypes as tf32 bits, sigma-permuted within each row:
// g_PT[chunk*16384 + class*128 + sigma(k)], chunks 0..2 = negs, 3 = positives.
__device__ __align__(16) uint32_t g_PT[4 * 128 * 128];

// k-permutation within each 8-block: pos = 2*(k&3) + ((k>>2)&1)
// => mma fragment pairs (k, k+4) are adjacent -> one LDS.64 per fragment.
__device__ __forceinline__ int sigma(int k) {
    return (k >> 3) * 8 + 2 * (k & 3) + ((k >> 2) & 1);
}

__device__ __forceinline__ uint32_t to_tf32(float f) {
    uint32_t u; asm("cvt.rna.tf32.f32 %0, %1;" : "=r"(u) : "f"(f)); return u;
}

__device__ __forceinline__ uint32_t smem_u32(const void* p) {
    uint32_t a;
    asm("{ .reg .u64 t; cvta.to.shared.u64 t, %1; cvt.u32.u64 %0, t; }" : "=r"(a) : "l"(p));
    return a;
}

__device__ __forceinline__ void cpa16(uint32_t dst, const void* src) {
    asm volatile("cp.async.ca.shared.global [%0], [%1], 16;" :: "r"(dst), "l"(src) : "memory");
}
#define CP_COMMIT() asm volatile("cp.async.commit_group;" ::: "memory")
#define CP_WAIT(n)  asm volatile("cp.async.wait_group %0;" :: "n"(n) : "memory")

// tf32 mma m16n8k8 (sm_80+, valid at base sm_103 target).
__device__ __forceinline__ void mma8(float* d, uint2 a01, uint2 a23, uint2 bv) {
    asm volatile(
        "mma.sync.aligned.m16n8k8.row.col.f32.tf32.tf32.f32 "
        "{%0,%1,%2,%3}, {%4,%5,%6,%7}, {%8,%9}, {%0,%1,%2,%3};"
        : "+f"(d[0]), "+f"(d[1]), "+f"(d[2]), "+f"(d[3])
        : "r"(a01.x), "r"(a23.x), "r"(a01.y), "r"(a23.y), "r"(bv.x), "r"(bv.y));
}

// ---------------------------------------------------------------------------
// Prep: normalize reps, build negatives, store tf32 sigma-permuted.
// ---------------------------------------------------------------------------
__global__ void dml_prep(const float* __restrict__ reps_w,
                         const float* __restrict__ fc_w,
                         const float* __restrict__ fc_b) {
    __shared__ float repn[128];
    __shared__ float red[128];
    const int c = blockIdx.x;
    const int d = threadIdx.x;

    float w = reps_w[c * 128 + d];
    red[d] = w * w;
    __syncthreads();
    for (int s = 64; s > 0; s >>= 1) { if (d < s) red[d] += red[d + s]; __syncthreads(); }
    float S = red[0];
    __syncthreads();
    float rn = w / fmaxf(sqrtf(S), 1e-12f);
    repn[d] = rn;
    g_PT[3 * 16384 + c * 128 + sigma(d)] = to_tf32(rn);
    __syncthreads();

    for (int n = 0; n < 3; n++) {
        const float* wr = fc_w + (size_t)(n * 128 + d) * 128;
        float a = fc_b[n * 128 + d];
        #pragma unroll 8
        for (int k = 0; k < 128; k++) a += repn[k] * wr[k];
        float v = a + rn;
        red[d] = v * v;
        __syncthreads();
        for (int s = 64; s > 0; s >>= 1) { if (d < s) red[d] += red[d + s]; __syncthreads(); }
        float S2 = red[0];
        __syncthreads();
        g_PT[n * 16384 + c * 128 + sigma(d)] = to_tf32(v / fmaxf(sqrtf(S2), 1e-12f));
    }
}

// ---------------------------------------------------------------------------
// Main: tf32 mma.sync GEMM [128px x 128k] x [128k x 512proto] + fused epilogue.
// grid = 1024 (8 b * 128 px-tiles of 128), block = 512 (16 warps), 1 CTA/SM.
// Warp tile: 32 classes x 32 px (2 m-tiles x 4 n-tiles): 4 cls-grp x 4 px-grp.
// Per s-step: 4 A + 4 B LDS.64 for 8 MMAs (balanced redundancy).
// pt double-buffered, prefetched with cp.async overlapping GEMM + epilogue.
// STRIDE 140: multiple of 4 words (16B cp.async + LDS.64 alignment) and
// 140 mod 32 = 12 -> gq rows hit distinct bank-quads: conflict-free frags.
// smem words: xs [0,17920) | pt0 [17920,35840) | pt1 [35840,53760)
//   red [53760,54272) | rs [54272,54400) | inv [54400,54528) | psm [54528,55040)
// total 55040 words = 220160 B.
// ---------------------------------------------------------------------------
#define STRIDE 140

__global__ __launch_bounds__(512, 1)
void dml_main(const float* __restrict__ x, float* __restrict__ out) {
    extern __shared__ float sm[];
    uint32_t* xs = (uint32_t*)sm;
    uint32_t* pt[2] = { (uint32_t*)(sm + 17920), (uint32_t*)(sm + 35840) };
    float* red = sm + 53760;    // 512
    float* rs  = sm + 54272;    // 128
    float* inv = sm + 54400;    // 128
    float* psm = sm + 54528;    // 512
    const uint32_t sbase = smem_u32(sm);
    const uint32_t ptb[2] = { sbase + 17920u * 4u, sbase + 35840u * 4u };

    const int tid  = threadIdx.x;
    const int wid  = tid >> 5;
    const int lane = tid & 31;
    const int gq   = lane >> 2;     // 0..7: class row within m-tile / B n-row
    const int jj   = lane & 3;      // 0..3: k-pair / px-pair index
    const int b    = blockIdx.x >> 7;
    const int hw0  = (blockIdx.x & 127) << 7;

    // ---- Prefetch proto chunks 0 and 1 (overlaps the transpose below) ----
    #pragma unroll
    for (int c2 = 0; c2 < 2; c2++) {
        const uint32_t* src = g_PT + c2 * 16384;
        #pragma unroll
        for (int i2 = 0; i2 < 8; i2++) {
            int i = i2 * 512 + tid;
            int row = i >> 5, c16 = i & 31;
            cpa16(ptb[c2] + (uint32_t)(row * STRIDE + c16 * 4) * 4u,
                  src + row * 128 + c16 * 4);
        }
        CP_COMMIT();
    }

    // ---- Transposed load: x[k][p] -> xs[p][sigma(k)], paired-k STS.64 ----
    {
        const float* xg = x + ((size_t)b * 128) * 16384 + hw0;
        const int p  = tid & 127;
        const int kq = tid >> 7;                 // k-quarter (32 k each)
        float ss = 0.f;
        #pragma unroll
        for (int j = 0; j < 16; j++) {
            int klo = kq * 32 + (j >> 2) * 8 + (j & 3);
            float v0 = xg[(size_t)klo * 16384 + p];
            float v1 = xg[(size_t)(klo + 4) * 16384 + p];
            ss += v0 * v0 + v1 * v1;
            uint2 u = { to_tf32(v0), to_tf32(v1) };
            // sigma(klo) even, sigma(klo+4) = sigma(klo)+1
            *(uint2*)(xs + p * STRIDE + (kq * 4 + (j >> 2)) * 8 + 2 * (j & 3)) = u;
        }
        red[tid] = ss;
    }
    __syncthreads();
    if (tid < 128)
        rs[tid] = 1.0f / fmaxf(sqrtf(red[tid] + red[tid + 128] +
                                     red[tid + 256] + red[tid + 384]), 1e-12f);

    const int cg = wid >> 2;           // class group 0..3
    const int pg = wid & 3;            // pixel group 0..3
    const int cw = cg * 32;            // warp class base
    const int pw = pg * 32;            // warp pixel base
    // thread's classes: cw + mt*16 + gq and +8;  px: pw + nt*8 + 2jj (+1)
    float mn[2][4][4];                 // min over negs [mt][nt][elem]

    for (int cc = 0; cc < 4; cc++) {
        if (cc < 3) { CP_WAIT(1); } else { CP_WAIT(0); }
        __syncthreads();

        // ---- GEMM: 16 k-steps, 2 m-tiles x 4 n-tiles, reg double-buffer ----
        const uint32_t* ap = pt[cc & 1] + (cw + gq) * STRIDE + 2 * jj;
        const uint32_t* bp = xs + (pw + gq) * STRIDE + 2 * jj;

        float acc[2][4][4];
        #pragma unroll
        for (int mt = 0; mt < 2; mt++)
            #pragma unroll
            for (int nt = 0; nt < 4; nt++)
                acc[mt][nt][0] = acc[mt][nt][1] = acc[mt][nt][2] = acc[mt][nt][3] = 0.f;

        uint2 av[4], bv[4];
        av[0] = *(const uint2*)(ap);
        av[1] = *(const uint2*)(ap + 8 * STRIDE);
        av[2] = *(const uint2*)(ap + 16 * STRIDE);
        av[3] = *(const uint2*)(ap + 24 * STRIDE);
        #pragma unroll
        for (int nt = 0; nt < 4; nt++)
            bv[nt] = *(const uint2*)(bp + nt * 8 * STRIDE);

        #pragma unroll
        for (int s = 0; s < 16; s++) {
            uint2 nav[4], nbv[4];
            if (s < 15) {
                const int o = (s + 1) * 8;
                nav[0] = *(const uint2*)(ap + o);
                nav[1] = *(const uint2*)(ap + 8 * STRIDE + o);
                nav[2] = *(const uint2*)(ap + 16 * STRIDE + o);
                nav[3] = *(const uint2*)(ap + 24 * STRIDE + o);
                #pragma unroll
                for (int nt = 0; nt < 4; nt++)
                    nbv[nt] = *(const uint2*)(bp + nt * 8 * STRIDE + o);
            }
            #pragma unroll
            for (int mt = 0; mt < 2; mt++)
                #pragma unroll
                for (int nt = 0; nt < 4; nt++)
                    mma8(acc[mt][nt], av[mt * 2], av[mt * 2 + 1], bv[nt]);
            if (s < 15) {
                #pragma unroll
                for (int q4 = 0; q4 < 4; q4++) { av[q4] = nav[q4]; bv[q4] = nbv[q4]; }
            }
        }

        __syncthreads();               // all warps done reading pt[cc&1]
        if (cc < 2) {                  // prefetch chunk cc+2 into freed buffer
            const uint32_t* src = g_PT + (cc + 2) * 16384;
            #pragma unroll
            for (int i2 = 0; i2 < 8; i2++) {
                int i = i2 * 512 + tid;
                int row = i >> 5, c16 = i & 31;
                cpa16(ptb[cc & 1] + (uint32_t)(row * STRIDE + c16 * 4) * 4u,
                      src + row * 128 + c16 * 4);
            }
            CP_COMMIT();
        }

        if (cc < 3) {
            // ---- Negatives: distances_neg + thread-local running min ----
            #pragma unroll
            for (int mt = 0; mt < 2; mt++)
                #pragma unroll
                for (int nt = 0; nt < 4; nt++) {
                    const int c0  = cw + mt * 16 + gq;
                    const int px0 = pw + nt * 8 + 2 * jj;
                    float2 rv = *(const float2*)(rs + px0);
                    float* a4 = acc[mt][nt];
                    float d00 = sqrtf(fmaxf(2.f - 2.f * a4[0] * rv.x, 1e-12f));
                    float d01 = sqrtf(fmaxf(2.f - 2.f * a4[1] * rv.y, 1e-12f));
                    float d10 = sqrtf(fmaxf(2.f - 2.f * a4[2] * rv.x, 1e-12f));
                    float d11 = sqrtf(fmaxf(2.f - 2.f * a4[3] * rv.y, 1e-12f));
                    float* m4 = mn[mt][nt];
                    if (cc == 0) {
                        m4[0] = d00; m4[1] = d01; m4[2] = d10; m4[3] = d11;
                    } else {
                        m4[0] = fminf(m4[0], d00); m4[1] = fminf(m4[1], d01);
                        m4[2] = fminf(m4[2], d10); m4[3] = fminf(m4[3], d11);
                    }
                    size_t base = 33554432u
                        + ((size_t)(b * 128 + c0) * 3 + cc) * 16384 + hw0 + px0;
                    __stcs((float2*)(out + base), make_float2(d00, d01));
                    __stcs((float2*)(out + base + (size_t)8 * 3 * 16384),
                           make_float2(d10, d11));
                }
        } else {
            // ---- Positives: distances, probs_ori, q; class-sum; cls_score ----
            float psum0[4] = {0.f, 0.f, 0.f, 0.f};   // per nt, even px
            float psum1[4] = {0.f, 0.f, 0.f, 0.f};   // per nt, odd px
            #pragma unroll
            for (int mt = 0; mt < 2; mt++)
                #pragma unroll
                for (int nt = 0; nt < 4; nt++) {
                    const int c0  = cw + mt * 16 + gq;
                    const int px0 = pw + nt * 8 + 2 * jj;
                    float2 rv = *(const float2*)(rs + px0);
                    float* a4 = acc[mt][nt];
                    float* m4 = mn[mt][nt];
                    float dst[4], ev[4];
                    #pragma unroll
                    for (int e = 0; e < 4; e++) {
                        float rsp = (e & 1) ? rv.y : rv.x;
                        float m  = fmaxf(2.f - 2.f * a4[e] * rsp, 1e-12f);
                        float d  = sqrtf(m);
                        float e1 = __expf(-m);
                        float tv = d + 0.3f * (2.f - m4[e]);
                        float p1 = __expf(-2.f * tv * tv);
                        dst[e] = d; ev[e] = e1;
                        a4[e] = e1 * p1;             // q, reuse acc
                        if (e & 1) psum1[nt] += p1; else psum0[nt] += p1;
                    }
                    size_t base0 = (size_t)(b * 128 + c0) * 16384 + hw0 + px0;
                    size_t base1 = base0 + (size_t)8 * 16384;
                    __stcs((float2*)(out + 16777216u + base0), make_float2(dst[0], dst[1]));
                    __stcs((float2*)(out + 16777216u + base1), make_float2(dst[2], dst[3]));
                    __stcs((float2*)(out + 83886080u + base0),
                           make_float2(ev[0] * ev[0], ev[1] * ev[1]));
                    __stcs((float2*)(out + 83886080u + base1),
                           make_float2(ev[2] * ev[2], ev[3] * ev[3]));
                }
            // warp-sum pr over the 32 classes (gq lanes), per nt px-pair
            #pragma unroll
            for (int nt = 0; nt < 4; nt++) {
                float p0 = psum0[nt], p1 = psum1[nt];
                p0 += __shfl_xor_sync(~0u, p0, 4);  p1 += __shfl_xor_sync(~0u, p1, 4);
                p0 += __shfl_xor_sync(~0u, p0, 8);  p1 += __shfl_xor_sync(~0u, p1, 8);
                p0 += __shfl_xor_sync(~0u, p0, 16); p1 += __shfl_xor_sync(~0u, p1, 16);
                if (gq == 0)
                    *(float2*)(psm + cg * 128 + pw + nt * 8 + 2 * jj) = make_float2(p0, p1);
            }
            __syncthreads();
            if (tid < 128)
                inv[tid] = 1.f / (psm[tid] + psm[128 + tid] +
                                  psm[256 + tid] + psm[384 + tid]);
            __syncthreads();
            #pragma unroll
            for (int mt = 0; mt < 2; mt++)
                #pragma unroll
                for (int nt = 0; nt < 4; nt++) {
                    const int c0  = cw + mt * 16 + gq;
                    const int px0 = pw + nt * 8 + 2 * jj;
                    float2 iv = *(const float2*)(inv + px0);
                    float* a4 = acc[mt][nt];
                    size_t base0 = (size_t)(b * 128 + c0) * 16384 + hw0 + px0;
                    __stcs((float2*)(out + base0),
                           make_float2(a4[0] * iv.x, a4[1] * iv.y));
                    __stcs((float2*)(out + base0 + (size_t)8 * 16384),
                           make_float2(a4[2] * iv.x, a4[3] * iv.y));
                }
        }
    }
}

// ---------------------------------------------------------------------------
extern "C" void kernel_launch(void* const* d_in, const int* in_sizes, int n_in,
                              void* d_out, int out_size) {
    const float* x    = (const float*)d_in[0];
    const float* reps = (const float*)d_in[1];
    const float* fcw  = (const float*)d_in[2];
    const float* fcb  = (const float*)d_in[3];
    float* out = (float*)d_out;

    const int smem = 55040 * (int)sizeof(float);   // 220160 B
    cudaFuncSetAttribute(dml_main, cudaFuncAttributeMaxDynamicSharedMemorySize, smem);

    dml_prep<<<128, 128>>>(reps, fcw, fcb);
    dml_main<<<1024, 512, smem>>>(x, out);
}

// round 14
// speedup vs baseline: 1.2540x; 1.2540x over previous
#include <cuda_runtime.h>
#include <cstdint>

// Problem constants:
//   x: [8, 128, 128, 128]  (B, D, H, W), HW = 16384, NPIX = 131072
//   C = 128, M = 1, NEG = 3  -> 512 prototypes total
// Output tuple flattened:
//   cls_score     @ 0         (16777216)
//   distances     @ 16777216  (16777216)
//   distances_neg @ 33554432  (50331648)
//   probs_ori     @ 83886080  (16777216)

typedef unsigned long long ull;

// Prototypes as tf32 bits, sigma-permuted within each row:
// g_PT[chunk*16384 + class*128 + sigma(k)], chunks 0..2 = negs, 3 = positives.
__device__ __align__(16) uint32_t g_PT[4 * 128 * 128];

// k-permutation within each 8-block: pos = 2*(k&3) + ((k>>2)&1)
// => mma fragment pairs (k, k+4) are adjacent -> one LDS.64 per fragment,
//    and k-quads {8t+2h, 8t+4+2h, 8t+1+2h, 8t+5+2h} are word-contiguous
//    -> STS.128 transpose stores.
__device__ __forceinline__ int sigma(int k) {
    return (k >> 3) * 8 + 2 * (k & 3) + ((k >> 2) & 1);
}

__device__ __forceinline__ uint32_t to_tf32(float f) {
    uint32_t u; asm("cvt.rna.tf32.f32 %0, %1;" : "=r"(u) : "f"(f)); return u;
}

__device__ __forceinline__ uint32_t smem_u32(const void* p) {
    uint32_t a;
    asm("{ .reg .u64 t; cvta.to.shared.u64 t, %1; cvt.u32.u64 %0, t; }" : "=r"(a) : "l"(p));
    return a;
}

__device__ __forceinline__ void cpa16(uint32_t dst, const void* src) {
    asm volatile("cp.async.ca.shared.global [%0], [%1], 16;" :: "r"(dst), "l"(src) : "memory");
}
#define CP_COMMIT() asm volatile("cp.async.commit_group;" ::: "memory")
#define CP_WAIT(n)  asm volatile("cp.async.wait_group %0;" :: "n"(n) : "memory")

// tf32 mma m16n8k8 (sm_80+, valid at base sm_103 target).
__device__ __forceinline__ void mma8(float* d, uint2 a01, uint2 a23, uint2 bv) {
    asm volatile(
        "mma.sync.aligned.m16n8k8.row.col.f32.tf32.tf32.f32 "
        "{%0,%1,%2,%3}, {%4,%5,%6,%7}, {%8,%9}, {%0,%1,%2,%3};"
        : "+f"(d[0]), "+f"(d[1]), "+f"(d[2]), "+f"(d[3])
        : "r"(a01.x), "r"(a23.x), "r"(a01.y), "r"(a23.y), "r"(bv.x), "r"(bv.y));
}

// ---------------------------------------------------------------------------
// Prep: normalize reps, build negatives, store tf32 sigma-permuted.
// ---------------------------------------------------------------------------
__global__ void dml_prep(const float* __restrict__ reps_w,
                         const float* __restrict__ fc_w,
                         const float* __restrict__ fc_b) {
    __shared__ float repn[128];
    __shared__ float red[128];
    const int c = blockIdx.x;
    const int d = threadIdx.x;

    float w = reps_w[c * 128 + d];
    red[d] = w * w;
    __syncthreads();
    for (int s = 64; s > 0; s >>= 1) { if (d < s) red[d] += red[d + s]; __syncthreads(); }
    float S = red[0];
    __syncthreads();
    float rn = w / fmaxf(sqrtf(S), 1e-12f);
    repn[d] = rn;
    g_PT[3 * 16384 + c * 128 + sigma(d)] = to_tf32(rn);
    __syncthreads();

    for (int n = 0; n < 3; n++) {
        const float* wr = fc_w + (size_t)(n * 128 + d) * 128;
        float a = fc_b[n * 128 + d];
        #pragma unroll 8
        for (int k = 0; k < 128; k++) a += repn[k] * wr[k];
        float v = a + rn;
        red[d] = v * v;
        __syncthreads();
        for (int s = 64; s > 0; s >>= 1) { if (d < s) red[d] += red[d + s]; __syncthreads(); }
        float S2 = red[0];
        __syncthreads();
        g_PT[n * 16384 + c * 128 + sigma(d)] = to_tf32(v / fmaxf(sqrtf(S2), 1e-12f));
    }
}

// ---------------------------------------------------------------------------
// Main: tf32 mma.sync GEMM [64px x 128k] x [128k x 512proto] + fused epilogue.
// grid = 2048 (8 b * 256 px-tiles of 64), block = 256 (8 warps), 2 CTAs/SM.
// Warp tile: 32 classes x 32 px (2 m x 4 n tiles); 4 cls-grp x 2 px-grp.
// Per s-step: 4 A + 4 B LDS.64 for 8 MMAs. No manual reg double-buffer
// (ptxas pipelines the unrolled loop; avoids the MOV storm seen in R13).
// STRIDE 136: fragment LDS conflict-free (gq rows at word offs {0,8,16,24}).
// Transpose uses quad-k STS.128 (sigma word-contiguity) - 4x fewer wavefronts.
// smem words: xs [0,8704) | pt [8704,26112) | red [26112,26368)
//   rs [26368,26432) | inv [26432,26496) | psm [26496,26752)
// total 26752 words = 107008 B -> 2 CTAs/SM.
// ---------------------------------------------------------------------------
#define STRIDE 136

__global__ __launch_bounds__(256, 2)
void dml_main(const float* __restrict__ x, float* __restrict__ out) {
    extern __shared__ float sm[];
    uint32_t* xs = (uint32_t*)sm;
    uint32_t* pt = (uint32_t*)(sm + 8704);
    float* red = sm + 26112;    // 256
    float* rs  = sm + 26368;    // 64
    float* inv = sm + 26432;    // 64
    float* psm = sm + 26496;    // 256
    const uint32_t sbase = smem_u32(sm);
    const uint32_t ptb   = sbase + 8704u * 4u;

    const int tid  = threadIdx.x;
    const int wid  = tid >> 5;
    const int lane = tid & 31;
    const int gq   = lane >> 2;     // 0..7: fragment row within tile
    const int jj   = lane & 3;      // 0..3: k-pair / px-pair index
    const int b    = blockIdx.x >> 8;
    const uint32_t hw0 = (blockIdx.x & 255) << 6;

    // ---- Prefetch proto chunk 0 (overlaps the transpose LDGs below) ----
    {
        const uint32_t* src = g_PT;
        #pragma unroll
        for (int i2 = 0; i2 < 16; i2++) {
            int i = i2 * 256 + tid;
            int row = i >> 5, c16 = i & 31;
            cpa16(ptb + (uint32_t)(row * STRIDE + c16 * 4) * 4u,
                  src + row * 128 + c16 * 4);
        }
        CP_COMMIT();
    }

    // ---- Transposed load: x[k][p] -> xs[p][sigma(k)], quad-k STS.128 ----
    {
        const float* xg = x + ((size_t)b * 128) * 16384 + hw0;
        const int p  = tid & 63;
        const int kq = tid >> 6;                 // k-quarter (32 k each)
        float ss = 0.f;
        #pragma unroll
        for (int j = 0; j < 8; j++) {
            const int t  = kq * 4 + (j >> 1);
            const int h2 = (j & 1) * 2;
            const int kb = t * 8 + h2;
            float v0 = xg[(size_t)(kb)     * 16384 + p];
            float v1 = xg[(size_t)(kb + 4) * 16384 + p];
            float v2 = xg[(size_t)(kb + 1) * 16384 + p];
            float v3 = xg[(size_t)(kb + 5) * 16384 + p];
            ss += v0 * v0 + v1 * v1 + v2 * v2 + v3 * v3;
            uint4 u = { to_tf32(v0), to_tf32(v1), to_tf32(v2), to_tf32(v3) };
            *(uint4*)(xs + p * STRIDE + t * 8 + h2 * 2) = u;
        }
        red[tid] = ss;
    }
    __syncthreads();
    if (tid < 64)
        rs[tid] = 1.0f / fmaxf(sqrtf(red[tid] + red[tid + 64] +
                                     red[tid + 128] + red[tid + 192]), 1e-12f);

    const int cg = wid >> 1;           // class group 0..3
    const int pg = wid & 1;            // pixel group 0..1
    const int cw = cg * 32;            // warp class base
    const int pw = pg * 32;            // warp pixel base
    float mn[2][4][4];                 // min over negs [mt][nt][elem]

    const uint32_t* ap = pt + (cw + gq) * STRIDE + 2 * jj;
    const uint32_t* bp = xs + (pw + gq) * STRIDE + 2 * jj;

    for (int cc = 0; cc < 4; cc++) {
        CP_WAIT(0);
        __syncthreads();

        // ---- GEMM: 16 k-steps, 2 m-tiles x 4 n-tiles ----
        float acc[2][4][4];
        #pragma unroll
        for (int mt = 0; mt < 2; mt++)
            #pragma unroll
            for (int nt = 0; nt < 4; nt++)
                acc[mt][nt][0] = acc[mt][nt][1] = acc[mt][nt][2] = acc[mt][nt][3] = 0.f;

        #pragma unroll
        for (int s = 0; s < 16; s++) {
            const int o = s * 8;
            uint2 av[4], bv[4];
            av[0] = *(const uint2*)(ap + o);
            av[1] = *(const uint2*)(ap + 8 * STRIDE + o);
            av[2] = *(const uint2*)(ap + 16 * STRIDE + o);
            av[3] = *(const uint2*)(ap + 24 * STRIDE + o);
            bv[0] = *(const uint2*)(bp + o);
            bv[1] = *(const uint2*)(bp + 8 * STRIDE + o);
            bv[2] = *(const uint2*)(bp + 16 * STRIDE + o);
            bv[3] = *(const uint2*)(bp + 24 * STRIDE + o);
            #pragma unroll
            for (int mt = 0; mt < 2; mt++)
                #pragma unroll
                for (int nt = 0; nt < 4; nt++)
                    mma8(acc[mt][nt], av[mt * 2], av[mt * 2 + 1], bv[nt]);
        }

        __syncthreads();               // all warps done reading pt
        if (cc < 3) {                  // load next chunk into the freed buffer
            const uint32_t* src = g_PT + (cc + 1) * 16384;
            #pragma unroll
            for (int i2 = 0; i2 < 16; i2++) {
                int i = i2 * 256 + tid;
                int row = i >> 5, c16 = i & 31;
                cpa16(ptb + (uint32_t)(row * STRIDE + c16 * 4) * 4u,
                      src + row * 128 + c16 * 4);
            }
            CP_COMMIT();
        }

        if (cc < 3) {
            // ---- Negatives: distances_neg + thread-local running min ----
            #pragma unroll
            for (int mt = 0; mt < 2; mt++)
                #pragma unroll
                for (int nt = 0; nt < 4; nt++) {
                    const int c0  = cw + mt * 16 + gq;
                    const int px0 = pw + nt * 8 + 2 * jj;
                    float2 rv = *(const float2*)(rs + px0);
                    float* a4 = acc[mt][nt];
                    float d00 = sqrtf(fmaxf(2.f - 2.f * a4[0] * rv.x, 1e-12f));
                    float d01 = sqrtf(fmaxf(2.f - 2.f * a4[1] * rv.y, 1e-12f));
                    float d10 = sqrtf(fmaxf(2.f - 2.f * a4[2] * rv.x, 1e-12f));
                    float d11 = sqrtf(fmaxf(2.f - 2.f * a4[3] * rv.y, 1e-12f));
                    float* m4 = mn[mt][nt];
                    if (cc == 0) {
                        m4[0] = d00; m4[1] = d01; m4[2] = d10; m4[3] = d11;
                    } else {
                        m4[0] = fminf(m4[0], d00); m4[1] = fminf(m4[1], d01);
                        m4[2] = fminf(m4[2], d10); m4[3] = fminf(m4[3], d11);
                    }
                    uint32_t base = 33554432u
                        + ((uint32_t)(b * 128 + c0) * 3 + cc) * 16384u + hw0 + px0;
                    __stcs((float2*)(out + base), make_float2(d00, d01));
                    __stcs((float2*)(out + base + 8u * 3u * 16384u),
                           make_float2(d10, d11));
                }
        } else {
            // ---- Positives: distances, probs_ori, q; class-sum; cls_score ----
            float psum0[4] = {0.f, 0.f, 0.f, 0.f};   // per nt, even px
            float psum1[4] = {0.f, 0.f, 0.f, 0.f};   // per nt, odd px
            #pragma unroll
            for (int mt = 0; mt < 2; mt++)
                #pragma unroll
                for (int nt = 0; nt < 4; nt++) {
                    const int c0  = cw + mt * 16 + gq;
                    const int px0 = pw + nt * 8 + 2 * jj;
                    float2 rv = *(const float2*)(rs + px0);
                    float* a4 = acc[mt][nt];
                    float* m4 = mn[mt][nt];
                    float dst[4], ev[4];
                    #pragma unroll
                    for (int e = 0; e < 4; e++) {
                        float rsp = (e & 1) ? rv.y : rv.x;
                        float m  = fmaxf(2.f - 2.f * a4[e] * rsp, 1e-12f);
                        float d  = sqrtf(m);
                        float e1 = __expf(-m);
                        float tv = d + 0.3f * (2.f - m4[e]);
                        float p1 = __expf(-2.f * tv * tv);
                        dst[e] = d; ev[e] = e1;
                        a4[e] = e1 * p1;             // q, reuse acc
                        if (e & 1) psum1[nt] += p1; else psum0[nt] += p1;
                    }
                    uint32_t base0 = (uint32_t)(b * 128 + c0) * 16384u + hw0 + px0;
                    uint32_t base1 = base0 + 8u * 16384u;
                    __stcs((float2*)(out + 16777216u + base0), make_float2(dst[0], dst[1]));
                    __stcs((float2*)(out + 16777216u + base1), make_float2(dst[2], dst[3]));
                    __stcs((float2*)(out + 83886080u + base0),
                           make_float2(ev[0] * ev[0], ev[1] * ev[1]));
                    __stcs((float2*)(out + 83886080u + base1),
                           make_float2(ev[2] * ev[2], ev[3] * ev[3]));
                }
            // warp-sum pr over the 32 classes (gq x mt), per nt px-pair
            #pragma unroll
            for (int nt = 0; nt < 4; nt++) {
                float p0 = psum0[nt], p1 = psum1[nt];
                p0 += __shfl_xor_sync(~0u, p0, 4);  p1 += __shfl_xor_sync(~0u, p1, 4);
                p0 += __shfl_xor_sync(~0u, p0, 8);  p1 += __shfl_xor_sync(~0u, p1, 8);
                p0 += __shfl_xor_sync(~0u, p0, 16); p1 += __shfl_xor_sync(~0u, p1, 16);
                if (gq == 0)
                    *(float2*)(psm + cg * 64 + pw + nt * 8 + 2 * jj) = make_float2(p0, p1);
            }
            __syncthreads();
            if (tid < 64)
                inv[tid] = 1.f / (psm[tid] + psm[64 + tid] +
                                  psm[128 + tid] + psm[192 + tid]);
            __syncthreads();
            #pragma unroll
            for (int mt = 0; mt < 2; mt++)
                #pragma unroll
                for (int nt = 0; nt < 4; nt++) {
                    const int c0  = cw + mt * 16 + gq;
                    const int px0 = pw + nt * 8 + 2 * jj;
                    float2 iv = *(const float2*)(inv + px0);
                    float* a4 = acc[mt][nt];
                    uint32_t base0 = (uint32_t)(b * 128 + c0) * 16384u + hw0 + px0;
                    __stcs((float2*)(out + base0),
                           make_float2(a4[0] * iv.x, a4[1] * iv.y));
                    __stcs((float2*)(out + base0 + 8u * 16384u),
                           make_float2(a4[2] * iv.x, a4[3] * iv.y));
                }
        }
    }
}

// ---------------------------------------------------------------------------
extern "C" void kernel_launch(void* const* d_in, const int* in_sizes, int n_in,
                              void* d_out, int out_size) {
    const float* x    = (const float*)d_in[0];
    const float* reps = (const float*)d_in[1];
    const float* fcw  = (const float*)d_in[2];
    const float* fcb  = (const float*)d_in[3];
    float* out = (float*)d_out;

    const int smem = 26752 * (int)sizeof(float);   // 107008 B
    cudaFuncSetAttribute(dml_main, cudaFuncAttributeMaxDynamicSharedMemorySize, smem);

    dml_prep<<<128, 128>>>(reps, fcw, fcb);
    dml_main<<<2048, 256, smem>>>(x, out);
}

// round 15
// speedup vs baseline: 1.5542x; 1.2394x over previous
#include <cuda_runtime.h>
#include <cuda_fp16.h>
#include <cstdint>

// Problem constants:
//   x: [8, 128, 128, 128]  (B, D, H, W), HW = 16384, NPIX = 131072
//   C = 128, M = 1, NEG = 3  -> 512 prototypes total
// Output tuple flattened:
//   cls_score     @ 0         (16777216)
//   distances     @ 16777216  (16777216)
//   distances_neg @ 33554432  (50331648)
//   probs_ori     @ 83886080  (16777216)

typedef unsigned long long ull;

// Prototypes as packed fp16 pairs (k-pairs), word tau-permuted:
// g_PH[chunk*8192 + class*64 + tau(w)], w = k>>1; chunks 0..2 negs, 3 pos.
__device__ __align__(16) uint32_t g_PH[4 * 128 * 64];

// word-level permutation within each 8-word block:
// tau(w) = blk*8 + 2*(w&3) + ((w>>2)&1)
// => fragment word pairs (w, w+4) (= k pairs (2w,2w+1),(2w+8,2w+9)) adjacent
//    -> one LDS.64 yields (a0,a2) or (b0,b1) for m16n8k16.
__device__ __forceinline__ int tau(int w) {
    return (w >> 3) * 8 + 2 * (w & 3) + ((w >> 2) & 1);
}

__device__ __forceinline__ uint32_t smem_u32(const void* p) {
    uint32_t a;
    asm("{ .reg .u64 t; cvta.to.shared.u64 t, %1; cvt.u32.u64 %0, t; }" : "=r"(a) : "l"(p));
    return a;
}

__device__ __forceinline__ void cpa16(uint32_t dst, const void* src) {
    asm volatile("cp.async.ca.shared.global [%0], [%1], 16;" :: "r"(dst), "l"(src) : "memory");
}
#define CP_COMMIT() asm volatile("cp.async.commit_group;" ::: "memory")
#define CP_WAIT(n)  asm volatile("cp.async.wait_group %0;" :: "n"(n) : "memory")

__device__ __forceinline__ uint32_t pkh2(float lo, float hi) {
    __half2 h = __floats2half2_rn(lo, hi);
    return *(uint32_t*)&h;
}

// fp16 mma m16n8k16, fp32 accumulate (sm_80+, valid at base sm_103 target).
// av0 = (a0,a2) row gq; av1 = (a1,a3) row gq+8; bv = (b0,b1).
__device__ __forceinline__ void mma16(float* d, uint2 av0, uint2 av1, uint2 bv) {
    asm volatile(
        "mma.sync.aligned.m16n8k16.row.col.f32.f16.f16.f32 "
        "{%0,%1,%2,%3}, {%4,%5,%6,%7}, {%8,%9}, {%0,%1,%2,%3};"
        : "+f"(d[0]), "+f"(d[1]), "+f"(d[2]), "+f"(d[3])
        : "r"(av0.x), "r"(av1.x), "r"(av0.y), "r"(av1.y), "r"(bv.x), "r"(bv.y));
}

// ---------------------------------------------------------------------------
// Prep: normalize reps, build negatives, store packed fp16 tau-permuted.
// ---------------------------------------------------------------------------
__global__ void dml_prep(const float* __restrict__ reps_w,
                         const float* __restrict__ fc_w,
                         const float* __restrict__ fc_b) {
    __shared__ float repn[128];
    __shared__ float vv[128];
    __shared__ float red[128];
    const int c = blockIdx.x;
    const int d = threadIdx.x;

    float w = reps_w[c * 128 + d];
    red[d] = w * w;
    __syncthreads();
    for (int s = 64; s > 0; s >>= 1) { if (d < s) red[d] += red[d + s]; __syncthreads(); }
    float S = red[0];
    __syncthreads();
    float rn = w / fmaxf(sqrtf(S), 1e-12f);
    repn[d] = rn;
    __syncthreads();
    if (d < 64)
        g_PH[3 * 8192 + c * 64 + tau(d)] = pkh2(repn[2 * d], repn[2 * d + 1]);

    for (int n = 0; n < 3; n++) {
        const float* wr = fc_w + (size_t)(n * 128 + d) * 128;
        float a = fc_b[n * 128 + d];
        #pragma unroll 8
        for (int k = 0; k < 128; k++) a += repn[k] * wr[k];
        float v = a + rn;
        red[d] = v * v;
        __syncthreads();
        for (int s = 64; s > 0; s >>= 1) { if (d < s) red[d] += red[d + s]; __syncthreads(); }
        float S2 = red[0];
        __syncthreads();
        vv[d] = v / fmaxf(sqrtf(S2), 1e-12f);
        __syncthreads();
        if (d < 64)
            g_PH[n * 8192 + c * 64 + tau(d)] = pkh2(vv[2 * d], vv[2 * d + 1]);
        __syncthreads();
    }
}

// ---------------------------------------------------------------------------
// Main: fp16 mma.sync GEMM [64px x 128k] x [128k x 512proto] + fused epilogue.
// grid = 2048 (8 b * 256 px-tiles of 64), block = 256 (8 warps), 2 CTAs/SM.
// Warp tile: 32 classes x 32 px (2 m x 4 n tiles of m16n8k16), 8 k-steps.
// Per s-step: 4 A + 4 B LDS.64 for 8 MMAs.
// pt double-buffered; chunk cc+2 prefetched right after GEMM cc.
// STRIDE 72 words: rows at bank offsets 8*gq -> conflict-free fragments.
// smem words: xs [0,4608) | pt0 [4608,13824) | pt1 [13824,23040)
//   red [23040,23296) | rs [23296,23360) | inv [23360,23424) | psm [23424,23680)
// total 23680 words = 94720 B -> 2 CTAs/SM.
// ---------------------------------------------------------------------------
#define STRIDE 72

__global__ __launch_bounds__(256, 2)
void dml_main(const float* __restrict__ x, float* __restrict__ out) {
    extern __shared__ float sm[];
    uint32_t* xs = (uint32_t*)sm;
    uint32_t* pt[2] = { (uint32_t*)(sm + 4608), (uint32_t*)(sm + 13824) };
    float* red = sm + 23040;    // 256
    float* rs  = sm + 23296;    // 64
    float* inv = sm + 23360;    // 64
    float* psm = sm + 23424;    // 256
    const uint32_t sbase = smem_u32(sm);
    const uint32_t ptb[2] = { sbase + 4608u * 4u, sbase + 13824u * 4u };

    const int tid  = threadIdx.x;
    const int wid  = tid >> 5;
    const int lane = tid & 31;
    const int gq   = lane >> 2;     // 0..7: fragment row
    const int jj   = lane & 3;      // 0..3: k-pair / px-pair index
    const int b    = blockIdx.x >> 8;
    const uint32_t hw0 = (blockIdx.x & 255) << 6;

    // ---- Prefetch proto chunks 0 and 1 (overlap transpose LDGs below) ----
    #pragma unroll
    for (int c2 = 0; c2 < 2; c2++) {
        const uint32_t* src = g_PH + c2 * 8192;
        #pragma unroll
        for (int i2 = 0; i2 < 8; i2++) {
            int i = i2 * 256 + tid;
            int row = i >> 4, c16 = i & 15;
            cpa16(ptb[c2] + (uint32_t)(row * STRIDE + c16 * 4) * 4u,
                  src + row * 64 + c16 * 4);
        }
        CP_COMMIT();
    }

    // ---- Transposed load: x[k][p] -> xs[p][tau(k>>1)] packed fp16 ----
    {
        const float* xg = x + ((size_t)b * 128) * 16384 + hw0;
        const int p  = tid & 63;
        const int kq = tid >> 6;                 // k-quarter (32 k each)
        float ss = 0.f;
        #pragma unroll
        for (int j = 0; j < 8; j++) {
            const int t = kq * 2 + (j >> 2);     // 8-word block index
            const int h = j & 3;
            const int k0 = 16 * t + 2 * h;       // word w1 = 8t+h
            const int k2 = k0 + 8;               // word w2 = 8t+4+h
            float v0 = xg[(size_t)(k0)     * 16384 + p];
            float v1 = xg[(size_t)(k0 + 1) * 16384 + p];
            float v2 = xg[(size_t)(k2)     * 16384 + p];
            float v3 = xg[(size_t)(k2 + 1) * 16384 + p];
            ss += v0 * v0 + v1 * v1 + v2 * v2 + v3 * v3;
            uint2 u = { pkh2(v0, v1), pkh2(v2, v3) };   // tau adjacency
            *(uint2*)(xs + p * STRIDE + 8 * t + 2 * h) = u;
        }
        red[tid] = ss;
    }
    __syncthreads();
    if (tid < 64)
        rs[tid] = 1.0f / fmaxf(sqrtf(red[tid] + red[tid + 64] +
                                     red[tid + 128] + red[tid + 192]), 1e-12f);

    const int cg = wid >> 1;           // class group 0..3
    const int pg = wid & 1;            // pixel group 0..1
    const int cw = cg * 32;            // warp class base
    const int pw = pg * 32;            // warp pixel base
    float mn[2][4][4];                 // min over negs [mt][nt][elem]

    const uint32_t* bp = xs + (pw + gq) * STRIDE + 2 * jj;

    for (int cc = 0; cc < 4; cc++) {
        if (cc < 3) { CP_WAIT(1); } else { CP_WAIT(0); }
        __syncthreads();

        // ---- GEMM: 8 k16-steps, 2 m-tiles x 4 n-tiles ----
        const uint32_t* ap = pt[cc & 1] + (cw + gq) * STRIDE + 2 * jj;
        float acc[2][4][4];
        #pragma unroll
        for (int mt = 0; mt < 2; mt++)
            #pragma unroll
            for (int nt = 0; nt < 4; nt++)
                acc[mt][nt][0] = acc[mt][nt][1] = acc[mt][nt][2] = acc[mt][nt][3] = 0.f;

        #pragma unroll
        for (int s = 0; s < 8; s++) {
            const int o = s * 8;
            uint2 av[4], bv[4];
            av[0] = *(const uint2*)(ap + o);
            av[1] = *(const uint2*)(ap + 8 * STRIDE + o);
            av[2] = *(const uint2*)(ap + 16 * STRIDE + o);
            av[3] = *(const uint2*)(ap + 24 * STRIDE + o);
            bv[0] = *(const uint2*)(bp + o);
            bv[1] = *(const uint2*)(bp + 8 * STRIDE + o);
            bv[2] = *(const uint2*)(bp + 16 * STRIDE + o);
            bv[3] = *(const uint2*)(bp + 24 * STRIDE + o);
            #pragma unroll
            for (int mt = 0; mt < 2; mt++)
                #pragma unroll
                for (int nt = 0; nt < 4; nt++)
                    mma16(acc[mt][nt], av[mt * 2], av[mt * 2 + 1], bv[nt]);
        }

        __syncthreads();               // all warps done reading pt[cc&1]
        if (cc < 2) {                  // prefetch chunk cc+2 into freed buffer
            const uint32_t* src = g_PH + (cc + 2) * 8192;
            #pragma unroll
            for (int i2 = 0; i2 < 8; i2++) {
                int i = i2 * 256 + tid;
                int row = i >> 4, c16 = i & 15;
                cpa16(ptb[cc & 1] + (uint32_t)(row * STRIDE + c16 * 4) * 4u,
                      src + row * 64 + c16 * 4);
            }
            CP_COMMIT();
        }

        if (cc < 3) {
            // ---- Negatives: distances_neg + thread-local running min ----
            #pragma unroll
            for (int mt = 0; mt < 2; mt++)
                #pragma unroll
                for (int nt = 0; nt < 4; nt++) {
                    const int c0  = cw + mt * 16 + gq;
                    const int px0 = pw + nt * 8 + 2 * jj;
                    float2 rv = *(const float2*)(rs + px0);
                    float* a4 = acc[mt][nt];
                    float d00 = sqrtf(fmaxf(2.f - 2.f * a4[0] * rv.x, 1e-12f));
                    float d01 = sqrtf(fmaxf(2.f - 2.f * a4[1] * rv.y, 1e-12f));
                    float d10 = sqrtf(fmaxf(2.f - 2.f * a4[2] * rv.x, 1e-12f));
                    float d11 = sqrtf(fmaxf(2.f - 2.f * a4[3] * rv.y, 1e-12f));
                    float* m4 = mn[mt][nt];
                    if (cc == 0) {
                        m4[0] = d00; m4[1] = d01; m4[2] = d10; m4[3] = d11;
                    } else {
                        m4[0] = fminf(m4[0], d00); m4[1] = fminf(m4[1], d01);
                        m4[2] = fminf(m4[2], d10); m4[3] = fminf(m4[3], d11);
                    }
                    uint32_t base = 33554432u
                        + ((uint32_t)(b * 128 + c0) * 3 + cc) * 16384u + hw0 + px0;
                    __stcs((float2*)(out + base), make_float2(d00, d01));
                    __stcs((float2*)(out + base + 8u * 3u * 16384u),
                           make_float2(d10, d11));
                }
        } else {
            // ---- Positives: distances, probs_ori, q; class-sum; cls_score ----
            float psum0[4] = {0.f, 0.f, 0.f, 0.f};
            float psum1[4] = {0.f, 0.f, 0.f, 0.f};
            #pragma unroll
            for (int mt = 0; mt < 2; mt++)
                #pragma unroll
                for (int nt = 0; nt < 4; nt++) {
                    const int c0  = cw + mt * 16 + gq;
                    const int px0 = pw + nt * 8 + 2 * jj;
                    float2 rv = *(const float2*)(rs + px0);
                    float* a4 = acc[mt][nt];
                    float* m4 = mn[mt][nt];
                    float dst[4], ev[4];
                    #pragma unroll
                    for (int e = 0; e < 4; e++) {
                        float rsp = (e & 1) ? rv.y : rv.x;
                        float m  = fmaxf(2.f - 2.f * a4[e] * rsp, 1e-12f);
                        float d  = sqrtf(m);
                        float e1 = __expf(-m);
                        float tv = d + 0.3f * (2.f - m4[e]);
                        float p1 = __expf(-2.f * tv * tv);
                        dst[e] = d; ev[e] = e1;
                        a4[e] = e1 * p1;             // q, reuse acc
                        if (e & 1) psum1[nt] += p1; else psum0[nt] += p1;
                    }
                    uint32_t base0 = (uint32_t)(b * 128 + c0) * 16384u + hw0 + px0;
                    uint32_t base1 = base0 + 8u * 16384u;
                    __stcs((float2*)(out + 16777216u + base0), make_float2(dst[0], dst[1]));
                    __stcs((float2*)(out + 16777216u + base1), make_float2(dst[2], dst[3]));
                    __stcs((float2*)(out + 83886080u + base0),
                           make_float2(ev[0] * ev[0], ev[1] * ev[1]));
                    __stcs((float2*)(out + 83886080u + base1),
                           make_float2(ev[2] * ev[2], ev[3] * ev[3]));
                }
            // warp-sum pr over the 32 classes (gq x mt), per nt px-pair
            #pragma unroll
            for (int nt = 0; nt < 4; nt++) {
                float p0 = psum0[nt], p1 = psum1[nt];
                p0 += __shfl_xor_sync(~0u, p0, 4);  p1 += __shfl_xor_sync(~0u, p1, 4);
                p0 += __shfl_xor_sync(~0u, p0, 8);  p1 += __shfl_xor_sync(~0u, p1, 8);
                p0 += __shfl_xor_sync(~0u, p0, 16); p1 += __shfl_xor_sync(~0u, p1, 16);
                if (gq == 0)
                    *(float2*)(psm + cg * 64 + pw + nt * 8 + 2 * jj) = make_float2(p0, p1);
            }
            __syncthreads();
            if (tid < 64)
                inv[tid] = 1.f / (psm[tid] + psm[64 + tid] +
                                  psm[128 + tid] + psm[192 + tid]);
            __syncthreads();
            #pragma unroll
            for (int mt = 0; mt < 2; mt++)
                #pragma unroll
                for (int nt = 0; nt < 4; nt++) {
                    const int c0  = cw + mt * 16 + gq;
                    const int px0 = pw + nt * 8 + 2 * jj;
                    float2 iv = *(const float2*)(inv + px0);
                    float* a4 = acc[mt][nt];
                    uint32_t base0 = (uint32_t)(b * 128 + c0) * 16384u + hw0 + px0;
                    __stcs((float2*)(out + base0),
                           make_float2(a4[0] * iv.x, a4[1] * iv.y));
                    __stcs((float2*)(out + base0 + 8u * 16384u),
                           make_float2(a4[2] * iv.x, a4[3] * iv.y));
                }
        }
    }
}

// ---------------------------------------------------------------------------
extern "C" void kernel_launch(void* const* d_in, const int* in_sizes, int n_in,
                              void* d_out, int out_size) {
    const float* x    = (const float*)d_in[0];
    const float* reps = (const float*)d_in[1];
    const float* fcw  = (const float*)d_in[2];
    const float* fcb  = (const float*)d_in[3];
    float* out = (float*)d_out;

    const int smem = 23680 * (int)sizeof(float);   // 94720 B
    cudaFuncSetAttribute(dml_main, cudaFuncAttributeMaxDynamicSharedMemorySize, smem);

    dml_prep<<<128, 128>>>(reps, fcw, fcb);
    dml_main<<<2048, 256, smem>>>(x, out);
}